// round 1
// baseline (speedup 1.0000x reference)
#include <cuda_runtime.h>
#include <math.h>

// ---------------- problem dims ----------------
#define BB   2
#define TQc  32
#define NQc  196
#define DQ   896
#define NQT  6272      // TQc*NQc  (query tokens per sample)
#define MQ   12544     // BB*NQT
#define NKT  2048      // kv tokens per sample (32*8*8)
#define MKV  4096      // BB*NKT
#define CIN  4
#define EMB  1024
#define HID  512
#define NH   4
#define HD   128
#define FFD  1024
#define OUTD 896

// ---------------- scratch (static device globals; no runtime alloc) -----
__device__ float g_qin[(size_t)MQ * HID];
__device__ float g_kv [(size_t)MKV * EMB];
__device__ float g_q  [(size_t)MQ * HID];
__device__ float g_k  [(size_t)MKV * HID];
__device__ float g_v  [(size_t)MKV * HID];
__device__ float g_s  [(size_t)BB * NH * NQT * NKT];   // attention scores, 8 slices
__device__ float g_o  [(size_t)MQ * HID];
__device__ float g_h  [(size_t)MQ * HID];
__device__ float g_ff [(size_t)MQ * FFD];
__device__ float g_h2 [(size_t)MQ * HID];

// ---------------- generic tiled SGEMM ----------------
// C[M,N] = act(A[M,K] @ B + bias), B is (K,N) row-major (TRANSB=0)
// or (N,K) row-major used transposed (TRANSB=1).
// Batched over blockIdx.z: z -> (bz = z/nhz, hz = z%nhz), pointer offsets
// A += bz*sAb + hz*sAh, etc.
template<int TRANSB, int ACT>
__global__ __launch_bounds__(256, 2)
void sgemm(const float* __restrict__ A, const float* __restrict__ Bm,
           const float* __restrict__ bias, float* __restrict__ C,
           int M, int N, int K, int lda, int ldb, int ldc,
           int nhz, long sAb, long sAh, long sBb, long sBh, long sCb, long sCh)
{
    int z  = blockIdx.z;
    int bz = z / nhz, hz = z % nhz;
    A  += bz * sAb + hz * sAh;
    Bm += bz * sBb + hz * sBh;
    C  += bz * sCb + hz * sCh;

    __shared__ float As[8][128];
    __shared__ float Bs[8][128];

    int tid = threadIdx.x;
    int tx = tid & 15, ty = tid >> 4;
    int row0 = blockIdx.y * 128, col0 = blockIdx.x * 128;

    float acc[8][8];
    #pragma unroll
    for (int i = 0; i < 8; i++)
        #pragma unroll
        for (int j = 0; j < 8; j++) acc[i][j] = 0.f;

    int arow = tid >> 1, ak0 = (tid & 1) * 4;   // A: 128 rows x 8 k
    for (int k0 = 0; k0 < K; k0 += 8) {
        // ---- stage A tile (transposed into As[k][m]) ----
        {
            int gr = row0 + arow;
            const float* ap = A + (long)gr * lda + (k0 + ak0);
            #pragma unroll
            for (int i = 0; i < 4; i++) {
                float vv = 0.f;
                if (gr < M && (k0 + ak0 + i) < K) vv = ap[i];
                As[ak0 + i][arow] = vv;
            }
        }
        // ---- stage B tile into Bs[k][n] ----
        if (!TRANSB) {
            int bk = tid >> 5, bn = (tid & 31) * 4;
            int gk = k0 + bk;
            const float* bp = Bm + (long)gk * ldb + (col0 + bn);
            #pragma unroll
            for (int i = 0; i < 4; i++) {
                float vv = 0.f;
                if (gk < K && (col0 + bn + i) < N) vv = bp[i];
                Bs[bk][bn + i] = vv;
            }
        } else {
            int bn = tid >> 1, bk0 = (tid & 1) * 4;
            int gn = col0 + bn;
            const float* bp = Bm + (long)gn * ldb + (k0 + bk0);
            #pragma unroll
            for (int i = 0; i < 4; i++) {
                float vv = 0.f;
                if (gn < N && (k0 + bk0 + i) < K) vv = bp[i];
                Bs[bk0 + i][bn] = vv;
            }
        }
        __syncthreads();

        #pragma unroll
        for (int kk = 0; kk < 8; kk++) {
            float a[8], b[8];
            #pragma unroll
            for (int i = 0; i < 8; i++) a[i] = As[kk][ty * 8 + i];
            #pragma unroll
            for (int j = 0; j < 8; j++) b[j] = Bs[kk][tx * 8 + j];
            #pragma unroll
            for (int i = 0; i < 8; i++)
                #pragma unroll
                for (int j = 0; j < 8; j++)
                    acc[i][j] = fmaf(a[i], b[j], acc[i][j]);
        }
        __syncthreads();
    }

    #pragma unroll
    for (int i = 0; i < 8; i++) {
        int gr = row0 + ty * 8 + i;
        if (gr >= M) continue;
        #pragma unroll
        for (int j = 0; j < 8; j++) {
            int gc = col0 + tx * 8 + j;
            if (gc >= N) continue;
            float vv = acc[i][j];
            if (bias) vv += bias[gc];
            if (ACT == 1) {  // jax.nn.gelu (approximate/tanh)
                float x3 = vv * vv * vv;
                vv = 0.5f * vv * (1.f + tanhf(0.7978845608028654f * (vv + 0.044715f * x3)));
            }
            C[(long)gr * ldc + gc] = vv;
        }
    }
}

// ---------------- 3D RoPE (analytic cos/sin) ----------------
// layout: rows of 512 = 4 heads x 128 dims; rotate pair (f, f+64) per head.
__device__ __forceinline__ void rope_pair(float* base, int f, float t, float py, float px)
{
    int sel = (f < 22) ? 0 : ((f < 43) ? 1 : 2);
    float pos = (sel == 0) ? t : ((sel == 1) ? py : px);
    // inv_freq = 10000^(-f/64) = 2^(-f*log2(10000)/64)
    float ang = pos * exp2f(-(float)f * 0.2076205059304601f);
    float c = cosf(ang), s = sinf(ang);
    float x0 = base[f], x1 = base[f + 64];
    base[f]      = x0 * c - x1 * s;
    base[f + 64] = x1 * c + x0 * s;
}

__global__ void rope_q(float* __restrict__ q)
{
    long idx = (long)blockIdx.x * blockDim.x + threadIdx.x;
    if (idx >= (long)MQ * NH * 64) return;
    int f    = (int)(idx & 63);
    int head = (int)((idx >> 6) & 3);
    long row = idx >> 8;
    int n = (int)(row % NQT);
    int t = n / NQc, g = n % NQc;
    rope_pair(q + row * HID + head * HD, f, (float)t, (float)(g / 14), (float)(g % 14));
}

__global__ void rope_k(float* __restrict__ k)
{
    long idx = (long)blockIdx.x * blockDim.x + threadIdx.x;
    if (idx >= (long)MKV * NH * 64) return;
    int f    = (int)(idx & 63);
    int head = (int)((idx >> 6) & 3);
    long row = idx >> 8;
    int n = (int)(row % NKT);
    int t = n / 64, g = n % 64;
    rope_pair(k + row * HID + head * HD, f, (float)t, (float)(g / 8), (float)(g % 8));
}

// ---------------- scaled stable softmax over rows of 2048 ----------------
__global__ void softmax_rows(float* __restrict__ S)
{
    long base = ((long)blockIdx.y * NQT + blockIdx.x) * NKT;
    float* p = S + base;
    int tid = threadIdx.x;                  // 256 threads, 8 elems each
    const float scale = 0.08838834764831845f;  // 1/sqrt(128)
    float v[8];
    float mx = -1e30f;
    #pragma unroll
    for (int i = 0; i < 8; i++) { v[i] = p[tid + 256 * i] * scale; mx = fmaxf(mx, v[i]); }
    __shared__ float red[8];
    #pragma unroll
    for (int o = 16; o > 0; o >>= 1) mx = fmaxf(mx, __shfl_xor_sync(~0u, mx, o));
    if ((tid & 31) == 0) red[tid >> 5] = mx;
    __syncthreads();
    float m = -1e30f;
    #pragma unroll
    for (int i = 0; i < 8; i++) m = fmaxf(m, red[i]);
    float s = 0.f;
    #pragma unroll
    for (int i = 0; i < 8; i++) { v[i] = __expf(v[i] - m); s += v[i]; }
    __syncthreads();
    #pragma unroll
    for (int o = 16; o > 0; o >>= 1) s += __shfl_xor_sync(~0u, s, o);
    if ((tid & 31) == 0) red[tid >> 5] = s;
    __syncthreads();
    float tot = 0.f;
    #pragma unroll
    for (int i = 0; i < 8; i++) tot += red[i];
    float inv = 1.f / tot;
    #pragma unroll
    for (int i = 0; i < 8; i++) p[tid + 256 * i] = v[i] * inv;
}

// ---------------- residual add + LayerNorm over 512 ----------------
__global__ void add_ln(const float* __restrict__ X, const float* __restrict__ Y,
                       const float* __restrict__ g, const float* __restrict__ b,
                       float* __restrict__ out)
{
    long row = blockIdx.x;
    const float* x = X + row * HID;
    const float* y = Y + row * HID;
    int tid = threadIdx.x;                  // 128 threads, 4 each
    float v[4]; float s = 0.f, s2 = 0.f;
    #pragma unroll
    for (int i = 0; i < 4; i++) {
        v[i] = x[tid + 128 * i] + y[tid + 128 * i];
        s += v[i]; s2 += v[i] * v[i];
    }
    __shared__ float rs[4], rs2[4];
    #pragma unroll
    for (int o = 16; o > 0; o >>= 1) {
        s  += __shfl_xor_sync(~0u, s, o);
        s2 += __shfl_xor_sync(~0u, s2, o);
    }
    if ((tid & 31) == 0) { rs[tid >> 5] = s; rs2[tid >> 5] = s2; }
    __syncthreads();
    s  = rs[0] + rs[1] + rs[2] + rs[3];
    s2 = rs2[0] + rs2[1] + rs2[2] + rs2[3];
    float mean = s * (1.f / HID);
    float var  = s2 * (1.f / HID) - mean * mean;
    float inv  = rsqrtf(var + 1e-5f);
    float* o = out + row * HID;
    #pragma unroll
    for (int i = 0; i < 4; i++) {
        int c = tid + 128 * i;
        o[c] = (v[i] - mean) * inv * g[c] + b[c];
    }
}

// ---------------- host orchestration ----------------
static inline dim3 ggrid(int M, int N, int Z)
{
    return dim3((N + 127) / 128, (M + 127) / 128, Z);
}

extern "C" void kernel_launch(void* const* d_in, const int* in_sizes, int n_in,
                              void* d_out, int out_size)
{
    (void)in_sizes; (void)n_in; (void)out_size;
    const float* x_in  = (const float*)d_in[0];
    const float* slow  = (const float*)d_in[1];
    /* d_in[2] frame_num: all-full, unused */
    const float* Wq_in = (const float*)d_in[3];
    const float* bq_in = (const float*)d_in[4];
    const float* Wm  = (const float*)d_in[5];
    const float* bm  = (const float*)d_in[6];
    const float* Wq  = (const float*)d_in[7];
    const float* bq  = (const float*)d_in[8];
    const float* Wk  = (const float*)d_in[9];
    const float* bk  = (const float*)d_in[10];
    const float* Wv  = (const float*)d_in[11];
    const float* bv  = (const float*)d_in[12];
    const float* Wo  = (const float*)d_in[13];
    const float* bo  = (const float*)d_in[14];
    const float* g1  = (const float*)d_in[15];
    const float* be1 = (const float*)d_in[16];
    const float* W1  = (const float*)d_in[17];
    const float* b1  = (const float*)d_in[18];
    const float* W2  = (const float*)d_in[19];
    const float* b2  = (const float*)d_in[20];
    const float* g2  = (const float*)d_in[21];
    const float* be2 = (const float*)d_in[22];
    const float* M1  = (const float*)d_in[23];
    const float* bm1 = (const float*)d_in[24];
    const float* M2  = (const float*)d_in[25];
    const float* bm2 = (const float*)d_in[26];
    float* out = (float*)d_out;

    float *qin, *kv, *q, *k, *v, *s, *o, *h, *ff, *h2;
    cudaGetSymbolAddress((void**)&qin, g_qin);
    cudaGetSymbolAddress((void**)&kv,  g_kv);
    cudaGetSymbolAddress((void**)&q,   g_q);
    cudaGetSymbolAddress((void**)&k,   g_k);
    cudaGetSymbolAddress((void**)&v,   g_v);
    cudaGetSymbolAddress((void**)&s,   g_s);
    cudaGetSymbolAddress((void**)&o,   g_o);
    cudaGetSymbolAddress((void**)&h,   g_h);
    cudaGetSymbolAddress((void**)&ff,  g_ff);
    cudaGetSymbolAddress((void**)&h2,  g_h2);

    // 1. q_in = slow @ Wq_in + bq_in               (12544x512, K=896)
    sgemm<0,0><<<ggrid(MQ, HID, 1), 256>>>(slow, Wq_in, bq_in, qin,
        MQ, HID, DQ, DQ, HID, HID, 1, 0,0,0,0,0,0);
    // 2. kv = x @ Wm + bm                          (4096x1024, K=4)
    sgemm<0,0><<<ggrid(MKV, EMB, 1), 256>>>(x_in, Wm, bm, kv,
        MKV, EMB, CIN, CIN, EMB, EMB, 1, 0,0,0,0,0,0);
    // 3. q = q_in @ Wq + bq
    sgemm<0,0><<<ggrid(MQ, HID, 1), 256>>>(qin, Wq, bq, q,
        MQ, HID, HID, HID, HID, HID, 1, 0,0,0,0,0,0);
    // 4/5. k, v = kv @ Wk/Wv + b
    sgemm<0,0><<<ggrid(MKV, HID, 1), 256>>>(kv, Wk, bk, k,
        MKV, HID, EMB, EMB, HID, HID, 1, 0,0,0,0,0,0);
    sgemm<0,0><<<ggrid(MKV, HID, 1), 256>>>(kv, Wv, bv, v,
        MKV, HID, EMB, EMB, HID, HID, 1, 0,0,0,0,0,0);
    // RoPE
    rope_q<<<(int)(((long)MQ * NH * 64 + 255) / 256), 256>>>(q);
    rope_k<<<(int)(((long)MKV * NH * 64 + 255) / 256), 256>>>(k);
    // 6. S = Qh @ Kh^T, batched over z = b*4+h     (6272x2048, K=128)
    sgemm<1,0><<<ggrid(NQT, NKT, BB * NH), 256>>>(q, k, (const float*)nullptr, s,
        NQT, NKT, HD, HID, HID, NKT,
        NH, (long)NQT * HID, (long)HD,
            (long)NKT * HID, (long)HD,
            (long)NH * NQT * NKT, (long)NQT * NKT);
    // softmax(scale * S)
    softmax_rows<<<dim3(NQT, BB * NH), 256>>>(s);
    // 7. O = P @ Vh                                 (6272x128, K=2048)
    sgemm<0,0><<<ggrid(NQT, HD, BB * NH), 256>>>(s, v, (const float*)nullptr, o,
        NQT, HD, NKT, NKT, HID, HID,
        NH, (long)NH * NQT * NKT, (long)NQT * NKT,
            (long)NKT * HID, (long)HD,
            (long)NQT * HID, (long)HD);
    // 8. o_proj = O @ Wo + bo   (reuse g_q as temp)
    sgemm<0,0><<<ggrid(MQ, HID, 1), 256>>>(o, Wo, bo, q,
        MQ, HID, HID, HID, HID, HID, 1, 0,0,0,0,0,0);
    // h = LN(q_in + o_proj)
    add_ln<<<MQ, 128>>>(qin, q, g1, be1, h);
    // FFN: gelu(h @ W1 + b1) @ W2 + b2   (reuse g_o as temp)
    sgemm<0,1><<<ggrid(MQ, FFD, 1), 256>>>(h, W1, b1, ff,
        MQ, FFD, HID, HID, FFD, FFD, 1, 0,0,0,0,0,0);
    sgemm<0,0><<<ggrid(MQ, HID, 1), 256>>>(ff, W2, b2, o,
        MQ, HID, FFD, FFD, HID, HID, 1, 0,0,0,0,0,0);
    // h2 = LN(h + ffn)
    add_ln<<<MQ, 128>>>(h, o, g2, be2, h2);
    // out MLP: gelu(h2 @ M1 + bm1) @ M2 + bm2 -> d_out
    sgemm<0,1><<<ggrid(MQ, FFD, 1), 256>>>(h2, M1, bm1, ff,
        MQ, FFD, HID, HID, FFD, FFD, 1, 0,0,0,0,0,0);
    sgemm<0,0><<<ggrid(MQ, OUTD, 1), 256>>>(ff, M2, bm2, out,
        MQ, OUTD, FFD, FFD, OUTD, OUTD, 1, 0,0,0,0,0,0);
}

// round 3
// speedup vs baseline: 3.3275x; 3.3275x over previous
#include <cuda_runtime.h>
#include <math.h>
#include <stdint.h>

// ---------------- problem dims ----------------
#define BB   2
#define TQc  32
#define NQc  196
#define DQ   896
#define NQT  6272
#define MQ   12544
#define NKT  2048
#define MKV  4096
#define CIN  4
#define EMB  1024
#define HID  512
#define NH   4
#define HD   128
#define FFD  1024
#define OUTD 896

// ---------------- scratch ----------------
__device__ float g_qin[(size_t)MQ * HID];
__device__ float g_kv [(size_t)MKV * EMB];
__device__ float g_q  [(size_t)MQ * HID];
__device__ float g_k  [(size_t)MKV * HID];
__device__ float g_v  [(size_t)MKV * HID];
__device__ float g_s  [(size_t)BB * NH * NQT * NKT];
__device__ float g_o  [(size_t)MQ * HID];
__device__ float g_h  [(size_t)MQ * HID];
__device__ float g_ff [(size_t)MQ * FFD];
__device__ float g_h2 [(size_t)MQ * HID];
// transposed weights [N,K]
__device__ float g_wqinT[512 * 896];
__device__ float g_wqT  [512 * 512];
__device__ float g_wkT  [512 * 1024];
__device__ float g_wvT  [512 * 1024];
__device__ float g_woT  [512 * 512];
__device__ float g_w1T  [1024 * 512];
__device__ float g_w2T  [512 * 1024];
__device__ float g_m1T  [1024 * 512];
__device__ float g_m2T  [896 * 1024];
__device__ float g_vt   [(size_t)BB * NH * HD * NKT];

// ---------------- tf32 helpers ----------------
__device__ __forceinline__ uint32_t f2tf(float x)
{
    uint32_t r;
    asm("cvt.rna.tf32.f32 %0, %1;" : "=r"(r) : "f"(x));
    return r;
}

__device__ __forceinline__ void mma_tf32(float* d, const uint32_t* a, const uint32_t* b)
{
    asm volatile(
        "mma.sync.aligned.m16n8k8.row.col.f32.tf32.tf32.f32 "
        "{%0,%1,%2,%3}, {%4,%5,%6,%7}, {%8,%9}, {%0,%1,%2,%3};\n"
        : "+f"(d[0]), "+f"(d[1]), "+f"(d[2]), "+f"(d[3])
        : "r"(a[0]), "r"(a[1]), "r"(a[2]), "r"(a[3]), "r"(b[0]), "r"(b[1]));
}

// ---------------- tf32 mma.sync GEMM ----------------
// C[M,N] = act(A[M,K] @ Bt[N,K]^T + bias). M%128==0, N%128==0, K%32==0.
// z-batched: z -> (bz = z/nhz, hz = z%nhz) with pointer strides.
// CTA: 256 thr = 8 warps (4x2), warp tile 32x64, K-tile 32 double-buffered.
#define TROW 36                         // padded row stride (floats) in smem
#define TILE_U32 (128 * TROW)           // 4608 u32 per tile
#define SMEM_BYTES (4 * TILE_U32 * 4)   // A/B x 2 buffers = 73728 B

__global__ void __launch_bounds__(256)
tgemm(const float* __restrict__ A, const float* __restrict__ Bt,
      const float* __restrict__ bias, float* __restrict__ C,
      int M, int N, int K, int lda, int ldb, int ldc,
      int nhz, long sAb, long sAh, long sBb, long sBh, long sCb, long sCh,
      int act)
{
    extern __shared__ __align__(16) uint32_t smem[];

    int z = blockIdx.z, bz = z / nhz, hz = z - bz * nhz;
    A  += bz * sAb + hz * sAh;
    Bt += bz * sBb + hz * sBh;
    C  += bz * sCb + hz * sCh;
    int m0 = blockIdx.y << 7, n0 = blockIdx.x << 7;

    int tid = threadIdx.x, wid = tid >> 5, lane = tid & 31;
    int wm = wid >> 1, wn = wid & 1;          // warp grid 4 (M) x 2 (N)
    int g = lane >> 2, tg = lane & 3;          // mma fragment coords

    // loader mapping: row = tid>>1 (0..127), col half = (tid&1)*16
    int lr = tid >> 1, lc = (tid & 1) << 4;
    const float* aptr = A + (long)(m0 + lr) * lda + lc;
    const float* bptr = Bt + (long)(n0 + lr) * ldb + lc;
    int sidx = lr * TROW + lc;

    uint32_t* Abuf[2] = { smem,                smem + 2 * TILE_U32 };
    uint32_t* Bbuf[2] = { smem + TILE_U32,     smem + 3 * TILE_U32 };

    float acc[2][8][4];
    #pragma unroll
    for (int i = 0; i < 2; i++)
        #pragma unroll
        for (int j = 0; j < 8; j++)
            #pragma unroll
            for (int c = 0; c < 4; c++) acc[i][j][c] = 0.f;

    int aRow = wm * 32 + g;     // smem row base for A fragments
    int bRow = wn * 64 + g;     // smem row base for B fragments

    float4 av[4], bv[4];
    // prologue: load k-tile 0
    #pragma unroll
    for (int i = 0; i < 4; i++) {
        av[i] = *(const float4*)(aptr + i * 4);
        bv[i] = *(const float4*)(bptr + i * 4);
    }
    #pragma unroll
    for (int i = 0; i < 4; i++) {
        uint4 ua = make_uint4(f2tf(av[i].x), f2tf(av[i].y), f2tf(av[i].z), f2tf(av[i].w));
        uint4 ub = make_uint4(f2tf(bv[i].x), f2tf(bv[i].y), f2tf(bv[i].z), f2tf(bv[i].w));
        *(uint4*)(Abuf[0] + sidx + i * 4) = ua;
        *(uint4*)(Bbuf[0] + sidx + i * 4) = ub;
    }
    __syncthreads();

    int nkt = K >> 5;
    for (int kt = 0; kt < nkt; kt++) {
        int buf = kt & 1;
        bool more = (kt + 1) < nkt;
        if (more) {
            int k0 = (kt + 1) << 5;
            #pragma unroll
            for (int i = 0; i < 4; i++) {
                av[i] = *(const float4*)(aptr + k0 + i * 4);
                bv[i] = *(const float4*)(bptr + k0 + i * 4);
            }
        }
        const uint32_t* Au = Abuf[buf];
        const uint32_t* Bu = Bbuf[buf];
        #pragma unroll
        for (int kk = 0; kk < 32; kk += 8) {
            uint32_t af[2][4], bf[8][2];
            #pragma unroll
            for (int i = 0; i < 2; i++) {
                int base = (aRow + i * 16) * TROW + kk + tg;
                af[i][0] = Au[base];
                af[i][1] = Au[base + 8 * TROW];
                af[i][2] = Au[base + 4];
                af[i][3] = Au[base + 8 * TROW + 4];
            }
            #pragma unroll
            for (int j = 0; j < 8; j++) {
                int base = (bRow + j * 8) * TROW + kk + tg;
                bf[j][0] = Bu[base];
                bf[j][1] = Bu[base + 4];
            }
            #pragma unroll
            for (int i = 0; i < 2; i++)
                #pragma unroll
                for (int j = 0; j < 8; j++)
                    mma_tf32(acc[i][j], af[i], bf[j]);
        }
        if (more) {
            uint32_t* Ad = Abuf[buf ^ 1];
            uint32_t* Bd = Bbuf[buf ^ 1];
            #pragma unroll
            for (int i = 0; i < 4; i++) {
                uint4 ua = make_uint4(f2tf(av[i].x), f2tf(av[i].y), f2tf(av[i].z), f2tf(av[i].w));
                uint4 ub = make_uint4(f2tf(bv[i].x), f2tf(bv[i].y), f2tf(bv[i].z), f2tf(bv[i].w));
                *(uint4*)(Ad + sidx + i * 4) = ua;
                *(uint4*)(Bd + sidx + i * 4) = ub;
            }
        }
        __syncthreads();
    }

    // epilogue: direct float2 stores per fragment
    #pragma unroll
    for (int i = 0; i < 2; i++) {
        int row0 = m0 + wm * 32 + i * 16 + g;
        #pragma unroll
        for (int j = 0; j < 8; j++) {
            int col = n0 + wn * 64 + j * 8 + 2 * tg;
            float b0 = 0.f, b1 = 0.f;
            if (bias) { b0 = bias[col]; b1 = bias[col + 1]; }
            #pragma unroll
            for (int half = 0; half < 2; half++) {
                float v0 = acc[i][j][half * 2]     + b0;
                float v1 = acc[i][j][half * 2 + 1] + b1;
                if (act) {
                    float x3 = v0 * v0 * v0;
                    v0 = 0.5f * v0 * (1.f + tanhf(0.7978845608028654f * (v0 + 0.044715f * x3)));
                    x3 = v1 * v1 * v1;
                    v1 = 0.5f * v1 * (1.f + tanhf(0.7978845608028654f * (v1 + 0.044715f * x3)));
                }
                *(float2*)(C + (long)(row0 + half * 8) * ldc + col) = make_float2(v0, v1);
            }
        }
    }
}

// ---------------- batched transpose: out[Cc,R] = in[R,Cc]^T ----------------
__global__ void transpose_k(const float* __restrict__ in, float* __restrict__ out,
                            int R, int Cc, int ldi, int ldo,
                            int nhz, long sInB, long sInH, long sOutB, long sOutH)
{
    int z = blockIdx.z, bz = z / nhz, hz = z - bz * nhz;
    in  += bz * sInB + hz * sInH;
    out += bz * sOutB + hz * sOutH;
    __shared__ float t[32][33];
    int c0 = blockIdx.x * 32, r0 = blockIdx.y * 32;
    int x = threadIdx.x, y = threadIdx.y;
    #pragma unroll
    for (int i = 0; i < 32; i += 8) {
        int r = r0 + y + i, c = c0 + x;
        t[y + i][x] = (r < R && c < Cc) ? in[(long)r * ldi + c] : 0.f;
    }
    __syncthreads();
    #pragma unroll
    for (int i = 0; i < 32; i += 8) {
        int r = c0 + y + i, c = r0 + x;
        if (r < Cc && c < R) out[(long)r * ldo + c] = t[x][y + i];
    }
}

// ---------------- kv input mapping (K=4, memory bound) ----------------
__global__ void kvmap(const float* __restrict__ x, const float* __restrict__ Wm,
                      const float* __restrict__ bm, float* __restrict__ kv)
{
    int gg = blockIdx.x * blockDim.x + threadIdx.x;
    if (gg >= MKV * 256) return;
    int m = gg >> 8, e4 = (gg & 255) << 2;
    float4 acc = *(const float4*)(bm + e4);
    #pragma unroll
    for (int c = 0; c < 4; c++) {
        float xv = x[m * 4 + c];
        float4 w = *(const float4*)(Wm + c * EMB + e4);
        acc.x += xv * w.x; acc.y += xv * w.y; acc.z += xv * w.z; acc.w += xv * w.w;
    }
    *(float4*)(kv + (long)m * EMB + e4) = acc;
}

// ---------------- 3D RoPE ----------------
__device__ __forceinline__ void rope_pair(float* base, int f, float t, float py, float px)
{
    int sel = (f < 22) ? 0 : ((f < 43) ? 1 : 2);
    float pos = (sel == 0) ? t : ((sel == 1) ? py : px);
    float ang = pos * exp2f(-(float)f * 0.2076205059304601f);
    float c = cosf(ang), s = sinf(ang);
    float x0 = base[f], x1 = base[f + 64];
    base[f]      = x0 * c - x1 * s;
    base[f + 64] = x1 * c + x0 * s;
}
__global__ void rope_q(float* __restrict__ q)
{
    long idx = (long)blockIdx.x * blockDim.x + threadIdx.x;
    if (idx >= (long)MQ * NH * 64) return;
    int f = (int)(idx & 63);
    int head = (int)((idx >> 6) & 3);
    long row = idx >> 8;
    int n = (int)(row % NQT);
    int t = n / NQc, g = n % NQc;
    rope_pair(q + row * HID + head * HD, f, (float)t, (float)(g / 14), (float)(g % 14));
}
__global__ void rope_k(float* __restrict__ k)
{
    long idx = (long)blockIdx.x * blockDim.x + threadIdx.x;
    if (idx >= (long)MKV * NH * 64) return;
    int f = (int)(idx & 63);
    int head = (int)((idx >> 6) & 3);
    long row = idx >> 8;
    int n = (int)(row % NKT);
    int t = n / 64, g = n % 64;
    rope_pair(k + row * HID + head * HD, f, (float)t, (float)(g / 8), (float)(g % 8));
}

// ---------------- scaled stable softmax over rows of 2048 ----------------
__global__ void softmax_rows(float* __restrict__ S)
{
    long base = ((long)blockIdx.y * NQT + blockIdx.x) * NKT;
    float* p = S + base;
    int tid = threadIdx.x;
    const float scale = 0.08838834764831845f;
    float v[8];
    float mx = -1e30f;
    #pragma unroll
    for (int i = 0; i < 8; i++) { v[i] = p[tid + 256 * i] * scale; mx = fmaxf(mx, v[i]); }
    __shared__ float red[8];
    #pragma unroll
    for (int o = 16; o > 0; o >>= 1) mx = fmaxf(mx, __shfl_xor_sync(~0u, mx, o));
    if ((tid & 31) == 0) red[tid >> 5] = mx;
    __syncthreads();
    float m = -1e30f;
    #pragma unroll
    for (int i = 0; i < 8; i++) m = fmaxf(m, red[i]);
    float s = 0.f;
    #pragma unroll
    for (int i = 0; i < 8; i++) { v[i] = __expf(v[i] - m); s += v[i]; }
    __syncthreads();
    #pragma unroll
    for (int o = 16; o > 0; o >>= 1) s += __shfl_xor_sync(~0u, s, o);
    if ((tid & 31) == 0) red[tid >> 5] = s;
    __syncthreads();
    float tot = 0.f;
    #pragma unroll
    for (int i = 0; i < 8; i++) tot += red[i];
    float inv = 1.f / tot;
    #pragma unroll
    for (int i = 0; i < 8; i++) p[tid + 256 * i] = v[i] * inv;
}

// ---------------- residual add + LayerNorm over 512 ----------------
__global__ void add_ln(const float* __restrict__ X, const float* __restrict__ Y,
                       const float* __restrict__ g, const float* __restrict__ b,
                       float* __restrict__ out)
{
    long row = blockIdx.x;
    const float* x = X + row * HID;
    const float* y = Y + row * HID;
    int tid = threadIdx.x;
    float v[4]; float s = 0.f, s2 = 0.f;
    #pragma unroll
    for (int i = 0; i < 4; i++) {
        v[i] = x[tid + 128 * i] + y[tid + 128 * i];
        s += v[i]; s2 += v[i] * v[i];
    }
    __shared__ float rs[4], rs2[4];
    #pragma unroll
    for (int o = 16; o > 0; o >>= 1) {
        s  += __shfl_xor_sync(~0u, s, o);
        s2 += __shfl_xor_sync(~0u, s2, o);
    }
    if ((tid & 31) == 0) { rs[tid >> 5] = s; rs2[tid >> 5] = s2; }
    __syncthreads();
    s  = rs[0] + rs[1] + rs[2] + rs[3];
    s2 = rs2[0] + rs2[1] + rs2[2] + rs2[3];
    float mean = s * (1.f / HID);
    float var  = s2 * (1.f / HID) - mean * mean;
    float inv  = rsqrtf(var + 1e-5f);
    float* o = out + row * HID;
    #pragma unroll
    for (int i = 0; i < 4; i++) {
        int c = tid + 128 * i;
        o[c] = (v[i] - mean) * inv * g[c] + b[c];
    }
}

// ---------------- host orchestration ----------------
static inline dim3 G(int M, int N, int Z) { return dim3(N >> 7, M >> 7, Z); }

extern "C" void kernel_launch(void* const* d_in, const int* in_sizes, int n_in,
                              void* d_out, int out_size)
{
    (void)in_sizes; (void)n_in; (void)out_size;
    const float* x_in  = (const float*)d_in[0];
    const float* slow  = (const float*)d_in[1];
    const float* Wq_in = (const float*)d_in[3];
    const float* bq_in = (const float*)d_in[4];
    const float* Wm  = (const float*)d_in[5];
    const float* bm  = (const float*)d_in[6];
    const float* Wq  = (const float*)d_in[7];
    const float* bq  = (const float*)d_in[8];
    const float* Wk  = (const float*)d_in[9];
    const float* bk  = (const float*)d_in[10];
    const float* Wv  = (const float*)d_in[11];
    const float* bv  = (const float*)d_in[12];
    const float* Wo  = (const float*)d_in[13];
    const float* bo  = (const float*)d_in[14];
    const float* g1  = (const float*)d_in[15];
    const float* be1 = (const float*)d_in[16];
    const float* W1  = (const float*)d_in[17];
    const float* b1  = (const float*)d_in[18];
    const float* W2  = (const float*)d_in[19];
    const float* b2  = (const float*)d_in[20];
    const float* g2  = (const float*)d_in[21];
    const float* be2 = (const float*)d_in[22];
    const float* M1  = (const float*)d_in[23];
    const float* bm1 = (const float*)d_in[24];
    const float* M2  = (const float*)d_in[25];
    const float* bm2 = (const float*)d_in[26];
    float* out = (float*)d_out;

    float *qin, *kv, *q, *k, *v, *s, *o, *h, *ff, *h2;
    float *wqinT, *wqT, *wkT, *wvT, *woT, *w1T, *w2T, *m1T, *m2T, *vt;
    cudaGetSymbolAddress((void**)&qin, g_qin);
    cudaGetSymbolAddress((void**)&kv,  g_kv);
    cudaGetSymbolAddress((void**)&q,   g_q);
    cudaGetSymbolAddress((void**)&k,   g_k);
    cudaGetSymbolAddress((void**)&v,   g_v);
    cudaGetSymbolAddress((void**)&s,   g_s);
    cudaGetSymbolAddress((void**)&o,   g_o);
    cudaGetSymbolAddress((void**)&h,   g_h);
    cudaGetSymbolAddress((void**)&ff,  g_ff);
    cudaGetSymbolAddress((void**)&h2,  g_h2);
    cudaGetSymbolAddress((void**)&wqinT, g_wqinT);
    cudaGetSymbolAddress((void**)&wqT,   g_wqT);
    cudaGetSymbolAddress((void**)&wkT,   g_wkT);
    cudaGetSymbolAddress((void**)&wvT,   g_wvT);
    cudaGetSymbolAddress((void**)&woT,   g_woT);
    cudaGetSymbolAddress((void**)&w1T,   g_w1T);
    cudaGetSymbolAddress((void**)&w2T,   g_w2T);
    cudaGetSymbolAddress((void**)&m1T,   g_m1T);
    cudaGetSymbolAddress((void**)&m2T,   g_m2T);
    cudaGetSymbolAddress((void**)&vt,    g_vt);

    static int smem_set = 0;
    if (!smem_set) {
        cudaFuncSetAttribute(tgemm, cudaFuncAttributeMaxDynamicSharedMemorySize, SMEM_BYTES);
        smem_set = 1;
    }

    dim3 tb(32, 8);
    // weight transposes: in[R=K, Cc=N] -> out[N, K]
    transpose_k<<<dim3(512/32, 896/32, 1), tb>>>(Wq_in, wqinT, 896, 512, 512, 896, 1, 0,0,0,0);
    transpose_k<<<dim3(512/32, 512/32, 1), tb>>>(Wq,    wqT,   512, 512, 512, 512, 1, 0,0,0,0);
    transpose_k<<<dim3(512/32, 1024/32,1), tb>>>(Wk,    wkT,  1024, 512, 512,1024, 1, 0,0,0,0);
    transpose_k<<<dim3(512/32, 1024/32,1), tb>>>(Wv,    wvT,  1024, 512, 512,1024, 1, 0,0,0,0);
    transpose_k<<<dim3(512/32, 512/32, 1), tb>>>(Wo,    woT,   512, 512, 512, 512, 1, 0,0,0,0);
    transpose_k<<<dim3(1024/32,512/32, 1), tb>>>(W1,    w1T,   512,1024,1024, 512, 1, 0,0,0,0);
    transpose_k<<<dim3(512/32, 1024/32,1), tb>>>(W2,    w2T,  1024, 512, 512,1024, 1, 0,0,0,0);
    transpose_k<<<dim3(1024/32,512/32, 1), tb>>>(M1,    m1T,   512,1024,1024, 512, 1, 0,0,0,0);
    transpose_k<<<dim3(896/32, 1024/32,1), tb>>>(M2,    m2T,  1024, 896, 896,1024, 1, 0,0,0,0);

    // 1. q_in = slow @ Wq_in + bq_in
    tgemm<<<G(MQ, HID, 1), 256, SMEM_BYTES>>>(slow, wqinT, bq_in, qin,
        MQ, HID, DQ, DQ, DQ, HID, 1, 0,0,0,0,0,0, 0);
    // 2. kv = x @ Wm + bm
    kvmap<<<(MKV * 256 + 255) / 256, 256>>>(x_in, Wm, bm, kv);
    // 3. q = q_in @ Wq + bq
    tgemm<<<G(MQ, HID, 1), 256, SMEM_BYTES>>>(qin, wqT, bq, q,
        MQ, HID, HID, HID, HID, HID, 1, 0,0,0,0,0,0, 0);
    // 4/5. k, v
    tgemm<<<G(MKV, HID, 1), 256, SMEM_BYTES>>>(kv, wkT, bk, k,
        MKV, HID, EMB, EMB, EMB, HID, 1, 0,0,0,0,0,0, 0);
    tgemm<<<G(MKV, HID, 1), 256, SMEM_BYTES>>>(kv, wvT, bv, v,
        MKV, HID, EMB, EMB, EMB, HID, 1, 0,0,0,0,0,0, 0);
    // RoPE
    rope_q<<<(int)(((long)MQ * NH * 64 + 255) / 256), 256>>>(q);
    rope_k<<<(int)(((long)MKV * NH * 64 + 255) / 256), 256>>>(k);
    // 6. S = Qh @ Kh^T  (z = b*4 + h)
    tgemm<<<G(NQT, NKT, BB * NH), 256, SMEM_BYTES>>>(q, k, (const float*)0, s,
        NQT, NKT, HD, HID, HID, NKT,
        NH, (long)NQT * HID, (long)HD, (long)NKT * HID, (long)HD,
            (long)NH * NQT * NKT, (long)NQT * NKT, 0);
    // softmax(scale * S)
    softmax_rows<<<dim3(NQT, BB * NH), 256>>>(s);
    // V transpose per head: vt[z][d][n]
    transpose_k<<<dim3(HD/32, NKT/32, BB * NH), tb>>>(v, vt, NKT, HD, HID, NKT,
        NH, (long)NKT * HID, (long)HD, (long)NH * HD * NKT, (long)HD * NKT);
    // 7. O = P @ V
    tgemm<<<G(NQT, HD, BB * NH), 256, SMEM_BYTES>>>(s, vt, (const float*)0, o,
        NQT, HD, NKT, NKT, NKT, HID,
        NH, (long)NH * NQT * NKT, (long)NQT * NKT,
            (long)NH * HD * NKT, (long)HD * NKT,
            (long)NQT * HID, (long)HD, 0);
    // 8. o_proj = O @ Wo + bo  (reuse q buffer)
    tgemm<<<G(MQ, HID, 1), 256, SMEM_BYTES>>>(o, woT, bo, q,
        MQ, HID, HID, HID, HID, HID, 1, 0,0,0,0,0,0, 0);
    // h = LN(q_in + o_proj)
    add_ln<<<MQ, 128>>>(qin, q, g1, be1, h);
    // FFN
    tgemm<<<G(MQ, FFD, 1), 256, SMEM_BYTES>>>(h, w1T, b1, ff,
        MQ, FFD, HID, HID, HID, FFD, 1, 0,0,0,0,0,0, 1);
    tgemm<<<G(MQ, HID, 1), 256, SMEM_BYTES>>>(ff, w2T, b2, o,
        MQ, HID, FFD, FFD, FFD, HID, 1, 0,0,0,0,0,0, 0);
    add_ln<<<MQ, 128>>>(h, o, g2, be2, h2);
    // output MLP
    tgemm<<<G(MQ, FFD, 1), 256, SMEM_BYTES>>>(h2, m1T, bm1, ff,
        MQ, FFD, HID, HID, HID, FFD, 1, 0,0,0,0,0,0, 1);
    tgemm<<<G(MQ, OUTD, 1), 256, SMEM_BYTES>>>(ff, m2T, bm2, out,
        MQ, OUTD, FFD, FFD, FFD, OUTD, 1, 0,0,0,0,0,0, 0);
}

// round 4
// speedup vs baseline: 3.4565x; 1.0388x over previous
#include <cuda_runtime.h>
#include <math.h>
#include <stdint.h>

// ---------------- problem dims ----------------
#define BB   2
#define TQc  32
#define NQc  196
#define DQ   896
#define NQT  6272
#define MQ   12544
#define NKT  2048
#define MKV  4096
#define CIN  4
#define EMB  1024
#define HID  512
#define NH   4
#define HD   128
#define FFD  1024
#define OUTD 896

// ---------------- scratch ----------------
__device__ float g_qin[(size_t)MQ * HID];
__device__ float g_kv [(size_t)MKV * EMB];
__device__ float g_q  [(size_t)MQ * HID];
__device__ float g_k  [(size_t)MKV * HID];
__device__ float g_v  [(size_t)MKV * HID];
__device__ float g_o  [(size_t)MQ * HID];
__device__ float g_h  [(size_t)MQ * HID];
__device__ float g_ff [(size_t)MQ * FFD];
__device__ float g_h2 [(size_t)MQ * HID];
// transposed weights [N,K]
__device__ float g_wqinT[512 * 896];
__device__ float g_wqT  [512 * 512];
__device__ float g_wkT  [512 * 1024];
__device__ float g_wvT  [512 * 1024];
__device__ float g_woT  [512 * 512];
__device__ float g_w1T  [1024 * 512];
__device__ float g_w2T  [512 * 1024];
__device__ float g_m1T  [1024 * 512];
__device__ float g_m2T  [896 * 1024];

// ---------------- tf32 helpers ----------------
__device__ __forceinline__ uint32_t f2tf(float x)
{
    uint32_t r;
    asm("cvt.rna.tf32.f32 %0, %1;" : "=r"(r) : "f"(x));
    return r;
}

__device__ __forceinline__ void mma_tf32(float* d, const uint32_t* a, const uint32_t* b)
{
    asm volatile(
        "mma.sync.aligned.m16n8k8.row.col.f32.tf32.tf32.f32 "
        "{%0,%1,%2,%3}, {%4,%5,%6,%7}, {%8,%9}, {%0,%1,%2,%3};\n"
        : "+f"(d[0]), "+f"(d[1]), "+f"(d[2]), "+f"(d[3])
        : "r"(a[0]), "r"(a[1]), "r"(a[2]), "r"(a[3]), "r"(b[0]), "r"(b[1]));
}

// =================================================================
// Fused flash attention (tf32 mma): per CTA: 128 q-rows x one (b,h),
// loop kv in tiles of 64; online softmax in registers; O accum in regs.
// Grid: (NQT/128, BB*NH), 256 threads (8 warps x 16 q-rows).
// =================================================================
#define QS_STRIDE 132
#define KS_STRIDE 132
#define VS_STRIDE 136
#define PS_STRIDE 68
#define QS_OFF 0
#define KS_OFF (128 * QS_STRIDE)                  // 16896
#define VS_OFF (KS_OFF + 64 * KS_STRIDE)          // 25344
#define PS_OFF (VS_OFF + 64 * VS_STRIDE)          // 34048
#define FLASH_SMEM ((PS_OFF + 128 * PS_STRIDE) * 4)   // 171008 B

__global__ void __launch_bounds__(256)
flash_attn(const float* __restrict__ gq, const float* __restrict__ gk,
           const float* __restrict__ gv, float* __restrict__ go)
{
    extern __shared__ float sm[];
    uint32_t* Qs = (uint32_t*)(sm + QS_OFF);
    uint32_t* Ks = (uint32_t*)(sm + KS_OFF);
    uint32_t* Vs = (uint32_t*)(sm + VS_OFF);
    uint32_t* Ps = (uint32_t*)(sm + PS_OFF);

    int b = blockIdx.y >> 2, h = blockIdx.y & 3;
    int hoff = h * HD;
    long qrow0 = (long)b * NQT + (long)blockIdx.x * 128;
    long kvrow0 = (long)b * NKT;

    int tid = threadIdx.x, w = tid >> 5, lane = tid & 31;
    int g = lane >> 2, tg = lane & 3;
    int wr = w * 16 + g;                      // warp-local q-row (and +8)

    // ---- stage Q tile (128 x 128) as tf32 ----
    {
        int row = tid >> 1, half = (tid & 1) << 6;
        const float* src = gq + (qrow0 + row) * HID + hoff + half;
        uint32_t* dst = Qs + row * QS_STRIDE + half;
        #pragma unroll
        for (int i = 0; i < 16; i++) {
            float4 v = *(const float4*)(src + i * 4);
            dst[i * 4 + 0] = f2tf(v.x); dst[i * 4 + 1] = f2tf(v.y);
            dst[i * 4 + 2] = f2tf(v.z); dst[i * 4 + 3] = f2tf(v.w);
        }
    }

    float Oacc[16][4];
    #pragma unroll
    for (int j = 0; j < 16; j++)
        #pragma unroll
        for (int c = 0; c < 4; c++) Oacc[j][c] = 0.f;
    float m0 = -1e30f, m1 = -1e30f, l0 = 0.f, l1 = 0.f;

    int kvr = tid >> 2, kseg = (tid & 3) << 5;    // loader: row 0..63, 32-col seg
    const float scale = 0.08838834764831845f;

    for (int jt = 0; jt < NKT / 64; jt++) {
        __syncthreads();   // previous tile's readers done
        // ---- stage K,V tiles (64 x 128) as tf32 ----
        {
            const float* ksrc = gk + (kvrow0 + jt * 64 + kvr) * HID + hoff + kseg;
            const float* vsrc = gv + (kvrow0 + jt * 64 + kvr) * HID + hoff + kseg;
            uint32_t* kd = Ks + kvr * KS_STRIDE + kseg;
            uint32_t* vd = Vs + kvr * VS_STRIDE + kseg;
            #pragma unroll
            for (int i = 0; i < 8; i++) {
                float4 kv4 = *(const float4*)(ksrc + i * 4);
                kd[i * 4 + 0] = f2tf(kv4.x); kd[i * 4 + 1] = f2tf(kv4.y);
                kd[i * 4 + 2] = f2tf(kv4.z); kd[i * 4 + 3] = f2tf(kv4.w);
                float4 vv4 = *(const float4*)(vsrc + i * 4);
                vd[i * 4 + 0] = f2tf(vv4.x); vd[i * 4 + 1] = f2tf(vv4.y);
                vd[i * 4 + 2] = f2tf(vv4.z); vd[i * 4 + 3] = f2tf(vv4.w);
            }
        }
        __syncthreads();

        // ---- S = Q . K^T  (16 q-rows x 64 kv) ----
        float S[8][4];
        #pragma unroll
        for (int j = 0; j < 8; j++)
            #pragma unroll
            for (int c = 0; c < 4; c++) S[j][c] = 0.f;
        {
            const uint32_t* Qw = Qs + wr * QS_STRIDE;
            #pragma unroll
            for (int kk = 0; kk < 128; kk += 8) {
                uint32_t af[4];
                af[0] = Qw[kk + tg];
                af[1] = Qw[8 * QS_STRIDE + kk + tg];
                af[2] = Qw[kk + tg + 4];
                af[3] = Qw[8 * QS_STRIDE + kk + tg + 4];
                #pragma unroll
                for (int j = 0; j < 8; j++) {
                    uint32_t bf[2];
                    const uint32_t* kb = Ks + (j * 8 + g) * KS_STRIDE + kk + tg;
                    bf[0] = kb[0];
                    bf[1] = kb[4];
                    mma_tf32(S[j], af, bf);
                }
            }
        }

        // ---- online softmax (rows g and g+8 of this warp) ----
        float mx0 = -1e30f, mx1 = -1e30f;
        #pragma unroll
        for (int j = 0; j < 8; j++) {
            #pragma unroll
            for (int c = 0; c < 4; c++) S[j][c] *= scale;
            mx0 = fmaxf(mx0, fmaxf(S[j][0], S[j][1]));
            mx1 = fmaxf(mx1, fmaxf(S[j][2], S[j][3]));
        }
        mx0 = fmaxf(mx0, __shfl_xor_sync(~0u, mx0, 1));
        mx0 = fmaxf(mx0, __shfl_xor_sync(~0u, mx0, 2));
        mx1 = fmaxf(mx1, __shfl_xor_sync(~0u, mx1, 1));
        mx1 = fmaxf(mx1, __shfl_xor_sync(~0u, mx1, 2));
        float mn0 = fmaxf(m0, mx0), mn1 = fmaxf(m1, mx1);
        float al0 = __expf(m0 - mn0), al1 = __expf(m1 - mn1);
        m0 = mn0; m1 = mn1;
        float sum0 = 0.f, sum1 = 0.f;
        uint32_t* prow0 = Ps + wr * PS_STRIDE;
        uint32_t* prow1 = Ps + (wr + 8) * PS_STRIDE;
        #pragma unroll
        for (int j = 0; j < 8; j++) {
            float p0 = __expf(S[j][0] - mn0);
            float p1 = __expf(S[j][1] - mn0);
            float p2 = __expf(S[j][2] - mn1);
            float p3 = __expf(S[j][3] - mn1);
            sum0 += p0 + p1; sum1 += p2 + p3;
            prow0[j * 8 + 2 * tg]     = f2tf(p0);
            prow0[j * 8 + 2 * tg + 1] = f2tf(p1);
            prow1[j * 8 + 2 * tg]     = f2tf(p2);
            prow1[j * 8 + 2 * tg + 1] = f2tf(p3);
        }
        sum0 += __shfl_xor_sync(~0u, sum0, 1);
        sum0 += __shfl_xor_sync(~0u, sum0, 2);
        sum1 += __shfl_xor_sync(~0u, sum1, 1);
        sum1 += __shfl_xor_sync(~0u, sum1, 2);
        l0 = l0 * al0 + sum0;
        l1 = l1 * al1 + sum1;
        #pragma unroll
        for (int j = 0; j < 16; j++) {
            Oacc[j][0] *= al0; Oacc[j][1] *= al0;
            Oacc[j][2] *= al1; Oacc[j][3] *= al1;
        }
        __syncwarp();

        // ---- O += P . V  (contraction over 64 kv) ----
        {
            const uint32_t* Pw = Ps + wr * PS_STRIDE;
            #pragma unroll
            for (int kk = 0; kk < 64; kk += 8) {
                uint32_t af[4];
                af[0] = Pw[kk + tg];
                af[1] = Pw[8 * PS_STRIDE + kk + tg];
                af[2] = Pw[kk + tg + 4];
                af[3] = Pw[8 * PS_STRIDE + kk + tg + 4];
                #pragma unroll
                for (int j2 = 0; j2 < 16; j2++) {
                    uint32_t bf[2];
                    const uint32_t* vb = Vs + (kk + tg) * VS_STRIDE + j2 * 8 + g;
                    bf[0] = vb[0];
                    bf[1] = vb[4 * VS_STRIDE];
                    mma_tf32(Oacc[j2], af, bf);
                }
            }
        }
    }

    // ---- epilogue: O / l -> g_o ----
    float inv0 = 1.f / l0, inv1 = 1.f / l1;
    float* obase0 = go + (qrow0 + wr) * HID + hoff;
    float* obase1 = go + (qrow0 + wr + 8) * HID + hoff;
    #pragma unroll
    for (int j2 = 0; j2 < 16; j2++) {
        *(float2*)(obase0 + j2 * 8 + 2 * tg) = make_float2(Oacc[j2][0] * inv0, Oacc[j2][1] * inv0);
        *(float2*)(obase1 + j2 * 8 + 2 * tg) = make_float2(Oacc[j2][2] * inv1, Oacc[j2][3] * inv1);
    }
}

// ---------------- tf32 mma.sync GEMM ----------------
// C[M,N] = act(A[M,K] @ Bt[N,K]^T + bias). M%128==0, N%128==0, K%32==0.
#define TROW 36
#define TILE_U32 (128 * TROW)
#define SMEM_BYTES (4 * TILE_U32 * 4)

__global__ void __launch_bounds__(256)
tgemm(const float* __restrict__ A, const float* __restrict__ Bt,
      const float* __restrict__ bias, float* __restrict__ C,
      int M, int N, int K, int lda, int ldb, int ldc, int act)
{
    extern __shared__ __align__(16) uint32_t smem[];

    int m0 = blockIdx.y << 7, n0 = blockIdx.x << 7;
    int tid = threadIdx.x, wid = tid >> 5, lane = tid & 31;
    int wm = wid >> 1, wn = wid & 1;
    int g = lane >> 2, tg = lane & 3;

    int lr = tid >> 1, lc = (tid & 1) << 4;
    const float* aptr = A + (long)(m0 + lr) * lda + lc;
    const float* bptr = Bt + (long)(n0 + lr) * ldb + lc;
    int sidx = lr * TROW + lc;

    uint32_t* Abuf[2] = { smem,            smem + 2 * TILE_U32 };
    uint32_t* Bbuf[2] = { smem + TILE_U32, smem + 3 * TILE_U32 };

    float acc[2][8][4];
    #pragma unroll
    for (int i = 0; i < 2; i++)
        #pragma unroll
        for (int j = 0; j < 8; j++)
            #pragma unroll
            for (int c = 0; c < 4; c++) acc[i][j][c] = 0.f;

    int aRow = wm * 32 + g;
    int bRow = wn * 64 + g;

    float4 av[4], bv[4];
    #pragma unroll
    for (int i = 0; i < 4; i++) {
        av[i] = *(const float4*)(aptr + i * 4);
        bv[i] = *(const float4*)(bptr + i * 4);
    }
    #pragma unroll
    for (int i = 0; i < 4; i++) {
        uint4 ua = make_uint4(f2tf(av[i].x), f2tf(av[i].y), f2tf(av[i].z), f2tf(av[i].w));
        uint4 ub = make_uint4(f2tf(bv[i].x), f2tf(bv[i].y), f2tf(bv[i].z), f2tf(bv[i].w));
        *(uint4*)(Abuf[0] + sidx + i * 4) = ua;
        *(uint4*)(Bbuf[0] + sidx + i * 4) = ub;
    }
    __syncthreads();

    int nkt = K >> 5;
    for (int kt = 0; kt < nkt; kt++) {
        int buf = kt & 1;
        bool more = (kt + 1) < nkt;
        if (more) {
            int k0 = (kt + 1) << 5;
            #pragma unroll
            for (int i = 0; i < 4; i++) {
                av[i] = *(const float4*)(aptr + k0 + i * 4);
                bv[i] = *(const float4*)(bptr + k0 + i * 4);
            }
        }
        const uint32_t* Au = Abuf[buf];
        const uint32_t* Bu = Bbuf[buf];
        #pragma unroll
        for (int kk = 0; kk < 32; kk += 8) {
            uint32_t af[2][4], bf[8][2];
            #pragma unroll
            for (int i = 0; i < 2; i++) {
                int base = (aRow + i * 16) * TROW + kk + tg;
                af[i][0] = Au[base];
                af[i][1] = Au[base + 8 * TROW];
                af[i][2] = Au[base + 4];
                af[i][3] = Au[base + 8 * TROW + 4];
            }
            #pragma unroll
            for (int j = 0; j < 8; j++) {
                int base = (bRow + j * 8) * TROW + kk + tg;
                bf[j][0] = Bu[base];
                bf[j][1] = Bu[base + 4];
            }
            #pragma unroll
            for (int i = 0; i < 2; i++)
                #pragma unroll
                for (int j = 0; j < 8; j++)
                    mma_tf32(acc[i][j], af[i], bf[j]);
        }
        if (more) {
            uint32_t* Ad = Abuf[buf ^ 1];
            uint32_t* Bd = Bbuf[buf ^ 1];
            #pragma unroll
            for (int i = 0; i < 4; i++) {
                uint4 ua = make_uint4(f2tf(av[i].x), f2tf(av[i].y), f2tf(av[i].z), f2tf(av[i].w));
                uint4 ub = make_uint4(f2tf(bv[i].x), f2tf(bv[i].y), f2tf(bv[i].z), f2tf(bv[i].w));
                *(uint4*)(Ad + sidx + i * 4) = ua;
                *(uint4*)(Bd + sidx + i * 4) = ub;
            }
        }
        __syncthreads();
    }

    #pragma unroll
    for (int i = 0; i < 2; i++) {
        int row0 = m0 + wm * 32 + i * 16 + g;
        #pragma unroll
        for (int j = 0; j < 8; j++) {
            int col = n0 + wn * 64 + j * 8 + 2 * tg;
            float b0 = 0.f, b1 = 0.f;
            if (bias) { b0 = bias[col]; b1 = bias[col + 1]; }
            #pragma unroll
            for (int half = 0; half < 2; half++) {
                float v0 = acc[i][j][half * 2]     + b0;
                float v1 = acc[i][j][half * 2 + 1] + b1;
                if (act) {
                    float x3 = v0 * v0 * v0;
                    v0 = 0.5f * v0 * (1.f + tanhf(0.7978845608028654f * (v0 + 0.044715f * x3)));
                    x3 = v1 * v1 * v1;
                    v1 = 0.5f * v1 * (1.f + tanhf(0.7978845608028654f * (v1 + 0.044715f * x3)));
                }
                *(float2*)(C + (long)(row0 + half * 8) * ldc + col) = make_float2(v0, v1);
            }
        }
    }
}

// ---------------- weight transpose: out[Cc,R] = in[R,Cc]^T ----------------
__global__ void transpose_k(const float* __restrict__ in, float* __restrict__ out,
                            int R, int Cc, int ldi, int ldo)
{
    __shared__ float t[32][33];
    int c0 = blockIdx.x * 32, r0 = blockIdx.y * 32;
    int x = threadIdx.x, y = threadIdx.y;
    #pragma unroll
    for (int i = 0; i < 32; i += 8) {
        int r = r0 + y + i, c = c0 + x;
        t[y + i][x] = (r < R && c < Cc) ? in[(long)r * ldi + c] : 0.f;
    }
    __syncthreads();
    #pragma unroll
    for (int i = 0; i < 32; i += 8) {
        int r = c0 + y + i, c = r0 + x;
        if (r < Cc && c < R) out[(long)r * ldo + c] = t[x][y + i];
    }
}

// ---------------- kv input mapping (K=4, memory bound) ----------------
__global__ void kvmap(const float* __restrict__ x, const float* __restrict__ Wm,
                      const float* __restrict__ bm, float* __restrict__ kv)
{
    int gg = blockIdx.x * blockDim.x + threadIdx.x;
    if (gg >= MKV * 256) return;
    int m = gg >> 8, e4 = (gg & 255) << 2;
    float4 acc = *(const float4*)(bm + e4);
    #pragma unroll
    for (int c = 0; c < 4; c++) {
        float xv = x[m * 4 + c];
        float4 w = *(const float4*)(Wm + c * EMB + e4);
        acc.x += xv * w.x; acc.y += xv * w.y; acc.z += xv * w.z; acc.w += xv * w.w;
    }
    *(float4*)(kv + (long)m * EMB + e4) = acc;
}

// ---------------- 3D RoPE ----------------
__device__ __forceinline__ void rope_pair(float* base, int f, float t, float py, float px)
{
    int sel = (f < 22) ? 0 : ((f < 43) ? 1 : 2);
    float pos = (sel == 0) ? t : ((sel == 1) ? py : px);
    float ang = pos * exp2f(-(float)f * 0.2076205059304601f);
    float c = cosf(ang), s = sinf(ang);
    float x0 = base[f], x1 = base[f + 64];
    base[f]      = x0 * c - x1 * s;
    base[f + 64] = x1 * c + x0 * s;
}
__global__ void rope_q(float* __restrict__ q)
{
    long idx = (long)blockIdx.x * blockDim.x + threadIdx.x;
    if (idx >= (long)MQ * NH * 64) return;
    int f = (int)(idx & 63);
    int head = (int)((idx >> 6) & 3);
    long row = idx >> 8;
    int n = (int)(row % NQT);
    int t = n / NQc, g = n % NQc;
    rope_pair(q + row * HID + head * HD, f, (float)t, (float)(g / 14), (float)(g % 14));
}
__global__ void rope_k(float* __restrict__ k)
{
    long idx = (long)blockIdx.x * blockDim.x + threadIdx.x;
    if (idx >= (long)MKV * NH * 64) return;
    int f = (int)(idx & 63);
    int head = (int)((idx >> 6) & 3);
    long row = idx >> 8;
    int n = (int)(row % NKT);
    int t = n / 64, g = n % 64;
    rope_pair(k + row * HID + head * HD, f, (float)t, (float)(g / 8), (float)(g % 8));
}

// ---------------- residual add + LayerNorm over 512 ----------------
__global__ void add_ln(const float* __restrict__ X, const float* __restrict__ Y,
                       const float* __restrict__ g, const float* __restrict__ b,
                       float* __restrict__ out)
{
    long row = blockIdx.x;
    const float* x = X + row * HID;
    const float* y = Y + row * HID;
    int tid = threadIdx.x;
    float v[4]; float s = 0.f, s2 = 0.f;
    #pragma unroll
    for (int i = 0; i < 4; i++) {
        v[i] = x[tid + 128 * i] + y[tid + 128 * i];
        s += v[i]; s2 += v[i] * v[i];
    }
    __shared__ float rs[4], rs2[4];
    #pragma unroll
    for (int o = 16; o > 0; o >>= 1) {
        s  += __shfl_xor_sync(~0u, s, o);
        s2 += __shfl_xor_sync(~0u, s2, o);
    }
    if ((tid & 31) == 0) { rs[tid >> 5] = s; rs2[tid >> 5] = s2; }
    __syncthreads();
    s  = rs[0] + rs[1] + rs[2] + rs[3];
    s2 = rs2[0] + rs2[1] + rs2[2] + rs2[3];
    float mean = s * (1.f / HID);
    float var  = s2 * (1.f / HID) - mean * mean;
    float inv  = rsqrtf(var + 1e-5f);
    float* o = out + row * HID;
    #pragma unroll
    for (int i = 0; i < 4; i++) {
        int c = tid + 128 * i;
        o[c] = (v[i] - mean) * inv * g[c] + b[c];
    }
}

// ---------------- host orchestration ----------------
static inline dim3 G(int M, int N) { return dim3(N >> 7, M >> 7); }

extern "C" void kernel_launch(void* const* d_in, const int* in_sizes, int n_in,
                              void* d_out, int out_size)
{
    (void)in_sizes; (void)n_in; (void)out_size;
    const float* x_in  = (const float*)d_in[0];
    const float* slow  = (const float*)d_in[1];
    const float* Wq_in = (const float*)d_in[3];
    const float* bq_in = (const float*)d_in[4];
    const float* Wm  = (const float*)d_in[5];
    const float* bm  = (const float*)d_in[6];
    const float* Wq  = (const float*)d_in[7];
    const float* bq  = (const float*)d_in[8];
    const float* Wk  = (const float*)d_in[9];
    const float* bk  = (const float*)d_in[10];
    const float* Wv  = (const float*)d_in[11];
    const float* bv  = (const float*)d_in[12];
    const float* Wo  = (const float*)d_in[13];
    const float* bo  = (const float*)d_in[14];
    const float* g1  = (const float*)d_in[15];
    const float* be1 = (const float*)d_in[16];
    const float* W1  = (const float*)d_in[17];
    const float* b1  = (const float*)d_in[18];
    const float* W2  = (const float*)d_in[19];
    const float* b2  = (const float*)d_in[20];
    const float* g2  = (const float*)d_in[21];
    const float* be2 = (const float*)d_in[22];
    const float* M1  = (const float*)d_in[23];
    const float* bm1 = (const float*)d_in[24];
    const float* M2  = (const float*)d_in[25];
    const float* bm2 = (const float*)d_in[26];
    float* out = (float*)d_out;

    float *qin, *kv, *q, *k, *v, *o, *h, *ff, *h2;
    float *wqinT, *wqT, *wkT, *wvT, *woT, *w1T, *w2T, *m1T, *m2T;
    cudaGetSymbolAddress((void**)&qin, g_qin);
    cudaGetSymbolAddress((void**)&kv,  g_kv);
    cudaGetSymbolAddress((void**)&q,   g_q);
    cudaGetSymbolAddress((void**)&k,   g_k);
    cudaGetSymbolAddress((void**)&v,   g_v);
    cudaGetSymbolAddress((void**)&o,   g_o);
    cudaGetSymbolAddress((void**)&h,   g_h);
    cudaGetSymbolAddress((void**)&ff,  g_ff);
    cudaGetSymbolAddress((void**)&h2,  g_h2);
    cudaGetSymbolAddress((void**)&wqinT, g_wqinT);
    cudaGetSymbolAddress((void**)&wqT,   g_wqT);
    cudaGetSymbolAddress((void**)&wkT,   g_wkT);
    cudaGetSymbolAddress((void**)&wvT,   g_wvT);
    cudaGetSymbolAddress((void**)&woT,   g_woT);
    cudaGetSymbolAddress((void**)&w1T,   g_w1T);
    cudaGetSymbolAddress((void**)&w2T,   g_w2T);
    cudaGetSymbolAddress((void**)&m1T,   g_m1T);
    cudaGetSymbolAddress((void**)&m2T,   g_m2T);

    static int attr_set = 0;
    if (!attr_set) {
        cudaFuncSetAttribute(tgemm, cudaFuncAttributeMaxDynamicSharedMemorySize, SMEM_BYTES);
        cudaFuncSetAttribute(flash_attn, cudaFuncAttributeMaxDynamicSharedMemorySize, FLASH_SMEM);
        attr_set = 1;
    }

    dim3 tb(32, 8);
    transpose_k<<<dim3(512/32, 896/32),  tb>>>(Wq_in, wqinT, 896, 512, 512, 896);
    transpose_k<<<dim3(512/32, 512/32),  tb>>>(Wq,    wqT,   512, 512, 512, 512);
    transpose_k<<<dim3(512/32, 1024/32), tb>>>(Wk,    wkT,  1024, 512, 512,1024);
    transpose_k<<<dim3(512/32, 1024/32), tb>>>(Wv,    wvT,  1024, 512, 512,1024);
    transpose_k<<<dim3(512/32, 512/32),  tb>>>(Wo,    woT,   512, 512, 512, 512);
    transpose_k<<<dim3(1024/32,512/32),  tb>>>(W1,    w1T,   512,1024,1024, 512);
    transpose_k<<<dim3(512/32, 1024/32), tb>>>(W2,    w2T,  1024, 512, 512,1024);
    transpose_k<<<dim3(1024/32,512/32),  tb>>>(M1,    m1T,   512,1024,1024, 512);
    transpose_k<<<dim3(896/32, 1024/32), tb>>>(M2,    m2T,  1024, 896, 896,1024);

    // 1. q_in = slow @ Wq_in + bq_in
    tgemm<<<G(MQ, HID), 256, SMEM_BYTES>>>(slow, wqinT, bq_in, qin,
        MQ, HID, DQ, DQ, DQ, HID, 0);
    // 2. kv = x @ Wm + bm
    kvmap<<<(MKV * 256 + 255) / 256, 256>>>(x_in, Wm, bm, kv);
    // 3. q = q_in @ Wq + bq
    tgemm<<<G(MQ, HID), 256, SMEM_BYTES>>>(qin, wqT, bq, q,
        MQ, HID, HID, HID, HID, HID, 0);
    // 4/5. k, v
    tgemm<<<G(MKV, HID), 256, SMEM_BYTES>>>(kv, wkT, bk, k,
        MKV, HID, EMB, EMB, EMB, HID, 0);
    tgemm<<<G(MKV, HID), 256, SMEM_BYTES>>>(kv, wvT, bv, v,
        MKV, HID, EMB, EMB, EMB, HID, 0);
    // RoPE
    rope_q<<<(int)(((long)MQ * NH * 64 + 255) / 256), 256>>>(q);
    rope_k<<<(int)(((long)MKV * NH * 64 + 255) / 256), 256>>>(k);
    // 6. fused attention -> g_o
    flash_attn<<<dim3(NQT / 128, BB * NH), 256, FLASH_SMEM>>>(q, k, v, o);
    // 7. o_proj = O @ Wo + bo  (reuse q buffer)
    tgemm<<<G(MQ, HID), 256, SMEM_BYTES>>>(o, woT, bo, q,
        MQ, HID, HID, HID, HID, HID, 0);
    // h = LN(q_in + o_proj)
    add_ln<<<MQ, 128>>>(qin, q, g1, be1, h);
    // FFN
    tgemm<<<G(MQ, FFD), 256, SMEM_BYTES>>>(h, w1T, b1, ff,
        MQ, FFD, HID, HID, HID, FFD, 1);
    tgemm<<<G(MQ, HID), 256, SMEM_BYTES>>>(ff, w2T, b2, o,
        MQ, HID, FFD, FFD, FFD, HID, 0);
    add_ln<<<MQ, 128>>>(h, o, g2, be2, h2);
    // output MLP
    tgemm<<<G(MQ, FFD), 256, SMEM_BYTES>>>(h2, m1T, bm1, ff,
        MQ, FFD, HID, HID, HID, FFD, 1);
    tgemm<<<G(MQ, OUTD), 256, SMEM_BYTES>>>(ff, m2T, bm2, out,
        MQ, OUTD, FFD, FFD, FFD, OUTD, 0);
}

// round 8
// speedup vs baseline: 4.9114x; 1.4209x over previous
#include <cuda_runtime.h>
#include <cuda_fp16.h>
#include <math.h>
#include <stdint.h>

// ---------------- problem dims ----------------
#define BB   2
#define TQc  32
#define NQc  196
#define DQ   896
#define NQT  6272
#define MQ   12544
#define NKT  2048
#define MKV  4096
#define CIN  4
#define EMB  1024
#define HID  512
#define NH   4
#define HD   128
#define FFD  1024
#define OUTD 896

// ---------------- scratch ----------------
__device__ float g_qin[(size_t)MQ * HID];
__device__ float g_kv [(size_t)MKV * EMB];
__device__ float g_q  [(size_t)MQ * HID];
__device__ float g_k  [(size_t)MKV * HID];
__device__ float g_v  [(size_t)MKV * HID];
__device__ float g_o  [(size_t)MQ * HID];
__device__ float g_h  [(size_t)MQ * HID];
__device__ float g_ff [(size_t)MQ * FFD];
__device__ float g_h2 [(size_t)MQ * HID];
__device__ float g_vt [(size_t)BB * NH * HD * NKT];
// transposed weights [N,K]
__device__ float g_wqinT[512 * 896];
__device__ float g_wqT  [512 * 512];
__device__ float g_wkT  [512 * 1024];
__device__ float g_wvT  [512 * 1024];
__device__ float g_woT  [512 * 512];
__device__ float g_w1T  [1024 * 512];
__device__ float g_w2T  [512 * 1024];
__device__ float g_m1T  [1024 * 512];
__device__ float g_m2T  [896 * 1024];

// ---------------- fp16 helpers ----------------
__device__ __forceinline__ uint32_t f2h2(float a, float b)
{
    __half2 h = __float22half2_rn(make_float2(a, b));
    return *(uint32_t*)&h;
}

__device__ __forceinline__ void mma_f16(float* d, const uint32_t* a, const uint32_t* b)
{
    asm volatile(
        "mma.sync.aligned.m16n8k16.row.col.f32.f16.f16.f32 "
        "{%0,%1,%2,%3}, {%4,%5,%6,%7}, {%8,%9}, {%0,%1,%2,%3};\n"
        : "+f"(d[0]), "+f"(d[1]), "+f"(d[2]), "+f"(d[3])
        : "r"(a[0]), "r"(a[1]), "r"(a[2]), "r"(a[3]), "r"(b[0]), "r"(b[1]));
}

// =================================================================
// Fused flash attention, fp16 mma m16n8k16.
// Grid (NQT/128, BB*NH), 256 thr (8 warps x 16 q-rows).
// =================================================================
#define FQ_W 68
#define FV_W 36
#define FLASH_WORDS (128*FQ_W + 64*FQ_W + 128*FV_W + 128*FV_W)
#define FLASH_SMEM (FLASH_WORDS * 4)   // 89088 B

__global__ void __launch_bounds__(256)
flash_attn(const float* __restrict__ gq, const float* __restrict__ gk,
           const float* __restrict__ gvt, float* __restrict__ go)
{
    extern __shared__ __align__(16) uint32_t sh[];
    uint32_t* Qs = sh;
    uint32_t* Ks = sh + 128 * FQ_W;
    uint32_t* Vs = Ks + 64 * FQ_W;
    uint32_t* Ps = Vs + 128 * FV_W;

    int b = blockIdx.y >> 2, h = blockIdx.y & 3;
    int hoff = h * HD;
    long qrow0 = (long)b * NQT + (long)blockIdx.x * 128;
    long kvrow0 = (long)b * NKT;
    const float* vtbase = gvt + (size_t)blockIdx.y * HD * NKT;

    int tid = threadIdx.x, w = tid >> 5, lane = tid & 31;
    int g = lane >> 2, tg = lane & 3;
    int wr = w * 16 + g;

    // ---- stage Q tile (128x128) as fp16 ----
    {
        int row = tid >> 1, fseg = (tid & 1) << 6;
        const float* src = gq + (qrow0 + row) * HID + hoff + fseg;
        uint32_t* dst = Qs + row * FQ_W + (fseg >> 1);
        #pragma unroll
        for (int i = 0; i < 8; i++) {
            float4 v0 = *(const float4*)(src + i * 8);
            float4 v1 = *(const float4*)(src + i * 8 + 4);
            uint4 u;
            u.x = f2h2(v0.x, v0.y); u.y = f2h2(v0.z, v0.w);
            u.z = f2h2(v1.x, v1.y); u.w = f2h2(v1.z, v1.w);
            *(uint4*)(dst + i * 4) = u;
        }
    }

    float Oacc[16][4];
    #pragma unroll
    for (int j = 0; j < 16; j++)
        #pragma unroll
        for (int c = 0; c < 4; c++) Oacc[j][c] = 0.f;
    float m0 = -1e30f, m1 = -1e30f, l0 = 0.f, l1 = 0.f;

    const float scale = 0.08838834764831845f;
    int kvr = tid >> 2, kfs = (tid & 3) << 5;
    int vr = tid >> 1, vfs = (tid & 1) << 5;

    for (int jt = 0; jt < NKT / 64; jt++) {
        __syncthreads();
        {
            const float* ksrc = gk + (kvrow0 + jt * 64 + kvr) * HID + hoff + kfs;
            uint32_t* kd = Ks + kvr * FQ_W + (kfs >> 1);
            #pragma unroll
            for (int i = 0; i < 4; i++) {
                float4 v0 = *(const float4*)(ksrc + i * 8);
                float4 v1 = *(const float4*)(ksrc + i * 8 + 4);
                uint4 u;
                u.x = f2h2(v0.x, v0.y); u.y = f2h2(v0.z, v0.w);
                u.z = f2h2(v1.x, v1.y); u.w = f2h2(v1.z, v1.w);
                *(uint4*)(kd + i * 4) = u;
            }
            const float* vsrc = vtbase + (size_t)vr * NKT + jt * 64 + vfs;
            uint32_t* vd = Vs + vr * FV_W + (vfs >> 1);
            #pragma unroll
            for (int i = 0; i < 4; i++) {
                float4 v0 = *(const float4*)(vsrc + i * 8);
                float4 v1 = *(const float4*)(vsrc + i * 8 + 4);
                uint4 u;
                u.x = f2h2(v0.x, v0.y); u.y = f2h2(v0.z, v0.w);
                u.z = f2h2(v1.x, v1.y); u.w = f2h2(v1.z, v1.w);
                *(uint4*)(vd + i * 4) = u;
            }
        }
        __syncthreads();

        // ---- S = Q.K^T ----
        float S[8][4];
        #pragma unroll
        for (int j = 0; j < 8; j++)
            #pragma unroll
            for (int c = 0; c < 4; c++) S[j][c] = 0.f;
        {
            const uint32_t* Qw = Qs + wr * FQ_W;
            #pragma unroll
            for (int kk2 = 0; kk2 < 64; kk2 += 8) {
                uint32_t af[4];
                af[0] = Qw[kk2 + tg];
                af[1] = Qw[8 * FQ_W + kk2 + tg];
                af[2] = Qw[kk2 + tg + 4];
                af[3] = Qw[8 * FQ_W + kk2 + tg + 4];
                #pragma unroll
                for (int j = 0; j < 8; j++) {
                    const uint32_t* kb = Ks + (j * 8 + g) * FQ_W + kk2 + tg;
                    uint32_t bf[2] = { kb[0], kb[4] };
                    mma_f16(S[j], af, bf);
                }
            }
        }

        // ---- online softmax ----
        float mx0 = -1e30f, mx1 = -1e30f;
        #pragma unroll
        for (int j = 0; j < 8; j++) {
            #pragma unroll
            for (int c = 0; c < 4; c++) S[j][c] *= scale;
            mx0 = fmaxf(mx0, fmaxf(S[j][0], S[j][1]));
            mx1 = fmaxf(mx1, fmaxf(S[j][2], S[j][3]));
        }
        mx0 = fmaxf(mx0, __shfl_xor_sync(~0u, mx0, 1));
        mx0 = fmaxf(mx0, __shfl_xor_sync(~0u, mx0, 2));
        mx1 = fmaxf(mx1, __shfl_xor_sync(~0u, mx1, 1));
        mx1 = fmaxf(mx1, __shfl_xor_sync(~0u, mx1, 2));
        float mn0 = fmaxf(m0, mx0), mn1 = fmaxf(m1, mx1);
        float al0 = __expf(m0 - mn0), al1 = __expf(m1 - mn1);
        m0 = mn0; m1 = mn1;
        float sum0 = 0.f, sum1 = 0.f;
        uint32_t* prow0 = Ps + wr * FV_W;
        uint32_t* prow1 = Ps + (wr + 8) * FV_W;
        #pragma unroll
        for (int j = 0; j < 8; j++) {
            float p0 = __expf(S[j][0] - mn0);
            float p1 = __expf(S[j][1] - mn0);
            float p2 = __expf(S[j][2] - mn1);
            float p3 = __expf(S[j][3] - mn1);
            sum0 += p0 + p1; sum1 += p2 + p3;
            prow0[4 * j + tg] = f2h2(p0, p1);
            prow1[4 * j + tg] = f2h2(p2, p3);
        }
        sum0 += __shfl_xor_sync(~0u, sum0, 1);
        sum0 += __shfl_xor_sync(~0u, sum0, 2);
        sum1 += __shfl_xor_sync(~0u, sum1, 1);
        sum1 += __shfl_xor_sync(~0u, sum1, 2);
        l0 = l0 * al0 + sum0;
        l1 = l1 * al1 + sum1;
        #pragma unroll
        for (int j = 0; j < 16; j++) {
            Oacc[j][0] *= al0; Oacc[j][1] *= al0;
            Oacc[j][2] *= al1; Oacc[j][3] *= al1;
        }
        __syncwarp();

        // ---- O += P.V ----
        {
            const uint32_t* Pw = Ps + wr * FV_W;
            #pragma unroll
            for (int kk2 = 0; kk2 < 32; kk2 += 8) {
                uint32_t af[4];
                af[0] = Pw[kk2 + tg];
                af[1] = Pw[8 * FV_W + kk2 + tg];
                af[2] = Pw[kk2 + tg + 4];
                af[3] = Pw[8 * FV_W + kk2 + tg + 4];
                #pragma unroll
                for (int j2 = 0; j2 < 16; j2++) {
                    const uint32_t* vb = Vs + (j2 * 8 + g) * FV_W + kk2 + tg;
                    uint32_t bf[2] = { vb[0], vb[4] };
                    mma_f16(Oacc[j2], af, bf);
                }
            }
        }
        __syncwarp();
    }

    float inv0 = 1.f / l0, inv1 = 1.f / l1;
    float* ob0 = go + (qrow0 + wr) * HID + hoff;
    float* ob1 = go + (qrow0 + wr + 8) * HID + hoff;
    #pragma unroll
    for (int j2 = 0; j2 < 16; j2++) {
        *(float2*)(ob0 + j2 * 8 + 2 * tg) = make_float2(Oacc[j2][0] * inv0, Oacc[j2][1] * inv0);
        *(float2*)(ob1 + j2 * 8 + 2 * tg) = make_float2(Oacc[j2][2] * inv1, Oacc[j2][3] * inv1);
    }
}

// ---------------- fp16 mma GEMM ----------------
#define TW 20
#define TILE_W (128 * TW)
#define GEMM_SMEM (4 * TILE_W * 4)

__global__ void __launch_bounds__(256)
tgemm(const float* __restrict__ A, const float* __restrict__ Bt,
      const float* __restrict__ bias, float* __restrict__ C,
      int M, int N, int K, int lda, int ldb, int ldc, int act)
{
    extern __shared__ __align__(16) uint32_t smem[];

    int m0 = blockIdx.y << 7, n0 = blockIdx.x << 7;
    int tid = threadIdx.x, wid = tid >> 5, lane = tid & 31;
    int wm = wid >> 1, wn = wid & 1;
    int g = lane >> 2, tg = lane & 3;

    int lr = tid >> 1, wc = (tid & 1) << 3;
    const float* aptr = A + (long)(m0 + lr) * lda + (wc << 1);
    const float* bptr = Bt + (long)(n0 + lr) * ldb + (wc << 1);
    int sidx = lr * TW + wc;

    uint32_t* Abuf[2] = { smem,          smem + 2 * TILE_W };
    uint32_t* Bbuf[2] = { smem + TILE_W, smem + 3 * TILE_W };

    float acc[2][8][4];
    #pragma unroll
    for (int i = 0; i < 2; i++)
        #pragma unroll
        for (int j = 0; j < 8; j++)
            #pragma unroll
            for (int c = 0; c < 4; c++) acc[i][j][c] = 0.f;

    int aRow = wm * 32 + g;
    int bRow = wn * 64 + g;

    float4 av[4], bv[4];
    #pragma unroll
    for (int i = 0; i < 4; i++) {
        av[i] = *(const float4*)(aptr + i * 4);
        bv[i] = *(const float4*)(bptr + i * 4);
    }
    {
        uint4 u;
        u.x = f2h2(av[0].x, av[0].y); u.y = f2h2(av[0].z, av[0].w);
        u.z = f2h2(av[1].x, av[1].y); u.w = f2h2(av[1].z, av[1].w);
        *(uint4*)(Abuf[0] + sidx) = u;
        u.x = f2h2(av[2].x, av[2].y); u.y = f2h2(av[2].z, av[2].w);
        u.z = f2h2(av[3].x, av[3].y); u.w = f2h2(av[3].z, av[3].w);
        *(uint4*)(Abuf[0] + sidx + 4) = u;
        u.x = f2h2(bv[0].x, bv[0].y); u.y = f2h2(bv[0].z, bv[0].w);
        u.z = f2h2(bv[1].x, bv[1].y); u.w = f2h2(bv[1].z, bv[1].w);
        *(uint4*)(Bbuf[0] + sidx) = u;
        u.x = f2h2(bv[2].x, bv[2].y); u.y = f2h2(bv[2].z, bv[2].w);
        u.z = f2h2(bv[3].x, bv[3].y); u.w = f2h2(bv[3].z, bv[3].w);
        *(uint4*)(Bbuf[0] + sidx + 4) = u;
    }
    __syncthreads();

    int nkt = K >> 5;
    for (int kt = 0; kt < nkt; kt++) {
        int buf = kt & 1;
        bool more = (kt + 1) < nkt;
        if (more) {
            int k0 = (kt + 1) << 5;
            #pragma unroll
            for (int i = 0; i < 4; i++) {
                av[i] = *(const float4*)(aptr + k0 + i * 4);
                bv[i] = *(const float4*)(bptr + k0 + i * 4);
            }
        }
        const uint32_t* Au = Abuf[buf];
        const uint32_t* Bu = Bbuf[buf];
        #pragma unroll
        for (int kk2 = 0; kk2 < 16; kk2 += 8) {
            uint32_t af[2][4], bf[8][2];
            #pragma unroll
            for (int i = 0; i < 2; i++) {
                int base = (aRow + i * 16) * TW + kk2 + tg;
                af[i][0] = Au[base];
                af[i][1] = Au[base + 8 * TW];
                af[i][2] = Au[base + 4];
                af[i][3] = Au[base + 8 * TW + 4];
            }
            #pragma unroll
            for (int j = 0; j < 8; j++) {
                int base = (bRow + j * 8) * TW + kk2 + tg;
                bf[j][0] = Bu[base];
                bf[j][1] = Bu[base + 4];
            }
            #pragma unroll
            for (int i = 0; i < 2; i++)
                #pragma unroll
                for (int j = 0; j < 8; j++)
                    mma_f16(acc[i][j], af[i], bf[j]);
        }
        if (more) {
            uint32_t* Ad = Abuf[buf ^ 1];
            uint32_t* Bd = Bbuf[buf ^ 1];
            uint4 u;
            u.x = f2h2(av[0].x, av[0].y); u.y = f2h2(av[0].z, av[0].w);
            u.z = f2h2(av[1].x, av[1].y); u.w = f2h2(av[1].z, av[1].w);
            *(uint4*)(Ad + sidx) = u;
            u.x = f2h2(av[2].x, av[2].y); u.y = f2h2(av[2].z, av[2].w);
            u.z = f2h2(av[3].x, av[3].y); u.w = f2h2(av[3].z, av[3].w);
            *(uint4*)(Ad + sidx + 4) = u;
            u.x = f2h2(bv[0].x, bv[0].y); u.y = f2h2(bv[0].z, bv[0].w);
            u.z = f2h2(bv[1].x, bv[1].y); u.w = f2h2(bv[1].z, bv[1].w);
            *(uint4*)(Bd + sidx) = u;
            u.x = f2h2(bv[2].x, bv[2].y); u.y = f2h2(bv[2].z, bv[2].w);
            u.z = f2h2(bv[3].x, bv[3].y); u.w = f2h2(bv[3].z, bv[3].w);
            *(uint4*)(Bd + sidx + 4) = u;
        }
        __syncthreads();
    }

    #pragma unroll
    for (int i = 0; i < 2; i++) {
        int row0 = m0 + wm * 32 + i * 16 + g;
        #pragma unroll
        for (int j = 0; j < 8; j++) {
            int col = n0 + wn * 64 + j * 8 + 2 * tg;
            float b0 = 0.f, b1 = 0.f;
            if (bias) { b0 = bias[col]; b1 = bias[col + 1]; }
            #pragma unroll
            for (int half = 0; half < 2; half++) {
                float v0 = acc[i][j][half * 2]     + b0;
                float v1 = acc[i][j][half * 2 + 1] + b1;
                if (act) {
                    float x3 = v0 * v0 * v0;
                    v0 = 0.5f * v0 * (1.f + tanhf(0.7978845608028654f * (v0 + 0.044715f * x3)));
                    x3 = v1 * v1 * v1;
                    v1 = 0.5f * v1 * (1.f + tanhf(0.7978845608028654f * (v1 + 0.044715f * x3)));
                }
                *(float2*)(C + (long)(row0 + half * 8) * ldc + col) = make_float2(v0, v1);
            }
        }
    }
}

// ---------------- weight transpose ----------------
__global__ void transpose_k(const float* __restrict__ in, float* __restrict__ out,
                            int R, int Cc, int ldi, int ldo)
{
    __shared__ float t[32][33];
    int c0 = blockIdx.x * 32, r0 = blockIdx.y * 32;
    int x = threadIdx.x, y = threadIdx.y;
    #pragma unroll
    for (int i = 0; i < 32; i += 8) {
        int r = r0 + y + i, c = c0 + x;
        t[y + i][x] = (r < R && c < Cc) ? in[(long)r * ldi + c] : 0.f;
    }
    __syncthreads();
    #pragma unroll
    for (int i = 0; i < 32; i += 8) {
        int r = c0 + y + i, c = r0 + x;
        if (r < Cc && c < R) out[(long)r * ldo + c] = t[x][y + i];
    }
}

// ---------------- V transpose: vt[z][d][kv] = v[b*NKT+kv][h*HD+d] ----------
__global__ void vtrans(const float* __restrict__ v, float* __restrict__ vt)
{
    __shared__ float t[32][33];
    int z = blockIdx.z;                   // b*NH + h
    int b = z >> 2, h = z & 3;
    int kv0 = blockIdx.x * 32, d0 = blockIdx.y * 32;
    int x = threadIdx.x, y = threadIdx.y;
    const float* src = v + ((long)b * NKT + kv0) * HID + h * HD + d0;
    #pragma unroll
    for (int i = 0; i < 32; i += 8)
        t[y + i][x] = src[(long)(y + i) * HID + x];   // t[kv][d]
    __syncthreads();
    float* dst = vt + ((size_t)z * HD + d0) * NKT + kv0;
    #pragma unroll
    for (int i = 0; i < 32; i += 8)
        dst[(long)(y + i) * NKT + x] = t[x][y + i];   // vt[d][kv]
}

// ---------------- kv input mapping ----------------
__global__ void kvmap(const float* __restrict__ x, const float* __restrict__ Wm,
                      const float* __restrict__ bm, float* __restrict__ kv)
{
    int gg = blockIdx.x * blockDim.x + threadIdx.x;
    if (gg >= MKV * 256) return;
    int m = gg >> 8, e4 = (gg & 255) << 2;
    float4 acc = *(const float4*)(bm + e4);
    #pragma unroll
    for (int c = 0; c < 4; c++) {
        float xv = x[m * 4 + c];
        float4 w = *(const float4*)(Wm + c * EMB + e4);
        acc.x += xv * w.x; acc.y += xv * w.y; acc.z += xv * w.z; acc.w += xv * w.w;
    }
    *(float4*)(kv + (long)m * EMB + e4) = acc;
}

// ---------------- 3D RoPE ----------------
__device__ __forceinline__ void rope_pair(float* base, int f, float t, float py, float px)
{
    int sel = (f < 22) ? 0 : ((f < 43) ? 1 : 2);
    float pos = (sel == 0) ? t : ((sel == 1) ? py : px);
    float ang = pos * exp2f(-(float)f * 0.2076205059304601f);
    float c = cosf(ang), s = sinf(ang);
    float x0 = base[f], x1 = base[f + 64];
    base[f]      = x0 * c - x1 * s;
    base[f + 64] = x1 * c + x0 * s;
}
__global__ void rope_q(float* __restrict__ q)
{
    long idx = (long)blockIdx.x * blockDim.x + threadIdx.x;
    if (idx >= (long)MQ * NH * 64) return;
    int f = (int)(idx & 63);
    int head = (int)((idx >> 6) & 3);
    long row = idx >> 8;
    int n = (int)(row % NQT);
    int t = n / NQc, g = n % NQc;
    rope_pair(q + row * HID + head * HD, f, (float)t, (float)(g / 14), (float)(g % 14));
}
__global__ void rope_k(float* __restrict__ k)
{
    long idx = (long)blockIdx.x * blockDim.x + threadIdx.x;
    if (idx >= (long)MKV * NH * 64) return;
    int f = (int)(idx & 63);
    int head = (int)((idx >> 6) & 3);
    long row = idx >> 8;
    int n = (int)(row % NKT);
    int t = n / 64, g = n % 64;
    rope_pair(k + row * HID + head * HD, f, (float)t, (float)(g / 8), (float)(g % 8));
}

// ---------------- residual add + LayerNorm ----------------
__global__ void add_ln(const float* __restrict__ X, const float* __restrict__ Y,
                       const float* __restrict__ g, const float* __restrict__ b,
                       float* __restrict__ out)
{
    long row = blockIdx.x;
    const float* x = X + row * HID;
    const float* y = Y + row * HID;
    int tid = threadIdx.x;
    float v[4]; float s = 0.f, s2 = 0.f;
    #pragma unroll
    for (int i = 0; i < 4; i++) {
        v[i] = x[tid + 128 * i] + y[tid + 128 * i];
        s += v[i]; s2 += v[i] * v[i];
    }
    __shared__ float rs[4], rs2[4];
    #pragma unroll
    for (int o = 16; o > 0; o >>= 1) {
        s  += __shfl_xor_sync(~0u, s, o);
        s2 += __shfl_xor_sync(~0u, s2, o);
    }
    if ((tid & 31) == 0) { rs[tid >> 5] = s; rs2[tid >> 5] = s2; }
    __syncthreads();
    s  = rs[0] + rs[1] + rs[2] + rs[3];
    s2 = rs2[0] + rs2[1] + rs2[2] + rs2[3];
    float mean = s * (1.f / HID);
    float var  = s2 * (1.f / HID) - mean * mean;
    float inv  = rsqrtf(var + 1e-5f);
    float* o = out + row * HID;
    #pragma unroll
    for (int i = 0; i < 4; i++) {
        int c = tid + 128 * i;
        o[c] = (v[i] - mean) * inv * g[c] + b[c];
    }
}

// ---------------- host orchestration ----------------
static inline dim3 G(int M, int N) { return dim3(N >> 7, M >> 7); }

extern "C" void kernel_launch(void* const* d_in, const int* in_sizes, int n_in,
                              void* d_out, int out_size)
{
    (void)in_sizes; (void)n_in; (void)out_size;
    const float* x_in  = (const float*)d_in[0];
    const float* slow  = (const float*)d_in[1];
    const float* Wq_in = (const float*)d_in[3];
    const float* bq_in = (const float*)d_in[4];
    const float* Wm  = (const float*)d_in[5];
    const float* bm  = (const float*)d_in[6];
    const float* Wq  = (const float*)d_in[7];
    const float* bq  = (const float*)d_in[8];
    const float* Wk  = (const float*)d_in[9];
    const float* bk  = (const float*)d_in[10];
    const float* Wv  = (const float*)d_in[11];
    const float* bv  = (const float*)d_in[12];
    const float* Wo  = (const float*)d_in[13];
    const float* bo  = (const float*)d_in[14];
    const float* g1  = (const float*)d_in[15];
    const float* be1 = (const float*)d_in[16];
    const float* W1  = (const float*)d_in[17];
    const float* b1  = (const float*)d_in[18];
    const float* W2  = (const float*)d_in[19];
    const float* b2  = (const float*)d_in[20];
    const float* g2  = (const float*)d_in[21];
    const float* be2 = (const float*)d_in[22];
    const float* M1  = (const float*)d_in[23];
    const float* bm1 = (const float*)d_in[24];
    const float* M2  = (const float*)d_in[25];
    const float* bm2 = (const float*)d_in[26];
    float* out = (float*)d_out;

    float *qin, *kv, *q, *k, *v, *o, *h, *ff, *h2, *vt;
    float *wqinT, *wqT, *wkT, *wvT, *woT, *w1T, *w2T, *m1T, *m2T;
    cudaGetSymbolAddress((void**)&qin, g_qin);
    cudaGetSymbolAddress((void**)&kv,  g_kv);
    cudaGetSymbolAddress((void**)&q,   g_q);
    cudaGetSymbolAddress((void**)&k,   g_k);
    cudaGetSymbolAddress((void**)&v,   g_v);
    cudaGetSymbolAddress((void**)&o,   g_o);
    cudaGetSymbolAddress((void**)&h,   g_h);
    cudaGetSymbolAddress((void**)&ff,  g_ff);
    cudaGetSymbolAddress((void**)&h2,  g_h2);
    cudaGetSymbolAddress((void**)&vt,  g_vt);
    cudaGetSymbolAddress((void**)&wqinT, g_wqinT);
    cudaGetSymbolAddress((void**)&wqT,   g_wqT);
    cudaGetSymbolAddress((void**)&wkT,   g_wkT);
    cudaGetSymbolAddress((void**)&wvT,   g_wvT);
    cudaGetSymbolAddress((void**)&woT,   g_woT);
    cudaGetSymbolAddress((void**)&w1T,   g_w1T);
    cudaGetSymbolAddress((void**)&w2T,   g_w2T);
    cudaGetSymbolAddress((void**)&m1T,   g_m1T);
    cudaGetSymbolAddress((void**)&m2T,   g_m2T);

    static int attr_set = 0;
    if (!attr_set) {
        cudaFuncSetAttribute(tgemm, cudaFuncAttributeMaxDynamicSharedMemorySize, GEMM_SMEM);
        cudaFuncSetAttribute(flash_attn, cudaFuncAttributeMaxDynamicSharedMemorySize, FLASH_SMEM);
        attr_set = 1;
    }

    dim3 tb(32, 8);
    // launches 0..4 (so launch idx 5 = big tgemm for ncu -s 5 -c 1)
    transpose_k<<<dim3(512/32, 896/32),  tb>>>(Wq_in, wqinT, 896, 512, 512, 896);
    kvmap<<<(MKV * 256 + 255) / 256, 256>>>(x_in, Wm, bm, kv);
    transpose_k<<<dim3(512/32, 512/32),  tb>>>(Wq, wqT,  512, 512, 512, 512);
    transpose_k<<<dim3(512/32, 1024/32), tb>>>(Wk, wkT, 1024, 512, 512,1024);
    transpose_k<<<dim3(512/32, 1024/32), tb>>>(Wv, wvT, 1024, 512, 512,1024);
    // 5: q_in = slow @ Wq_in + bq_in   <- ncu profile target
    tgemm<<<G(MQ, HID), 256, GEMM_SMEM>>>(slow, wqinT, bq_in, qin,
        MQ, HID, DQ, DQ, DQ, HID, 0);
    // remaining weight transposes
    transpose_k<<<dim3(512/32, 512/32),  tb>>>(Wo, woT,  512, 512, 512, 512);
    transpose_k<<<dim3(1024/32,512/32),  tb>>>(W1, w1T,  512,1024,1024, 512);
    transpose_k<<<dim3(512/32, 1024/32), tb>>>(W2, w2T, 1024, 512, 512,1024);
    transpose_k<<<dim3(1024/32,512/32),  tb>>>(M1, m1T,  512,1024,1024, 512);
    transpose_k<<<dim3(896/32, 1024/32), tb>>>(M2, m2T, 1024, 896, 896,1024);
    // projections
    tgemm<<<G(MQ, HID), 256, GEMM_SMEM>>>(qin, wqT, bq, q,
        MQ, HID, HID, HID, HID, HID, 0);
    tgemm<<<G(MKV, HID), 256, GEMM_SMEM>>>(kv, wkT, bk, k,
        MKV, HID, EMB, EMB, EMB, HID, 0);
    tgemm<<<G(MKV, HID), 256, GEMM_SMEM>>>(kv, wvT, bv, v,
        MKV, HID, EMB, EMB, EMB, HID, 0);
    // RoPE
    rope_q<<<(int)(((long)MQ * NH * 64 + 255) / 256), 256>>>(q);
    rope_k<<<(int)(((long)MKV * NH * 64 + 255) / 256), 256>>>(k);
    // V transpose per (b,h)
    vtrans<<<dim3(NKT/32, HD/32, BB * NH), tb>>>(v, vt);
    // fused attention
    flash_attn<<<dim3(NQT / 128, BB * NH), 256, FLASH_SMEM>>>(q, k, vt, o);
    // o_proj (reuse q)
    tgemm<<<G(MQ, HID), 256, GEMM_SMEM>>>(o, woT, bo, q,
        MQ, HID, HID, HID, HID, HID, 0);
    add_ln<<<MQ, 128>>>(qin, q, g1, be1, h);
    tgemm<<<G(MQ, FFD), 256, GEMM_SMEM>>>(h, w1T, b1, ff,
        MQ, FFD, HID, HID, HID, FFD, 1);
    tgemm<<<G(MQ, HID), 256, GEMM_SMEM>>>(ff, w2T, b2, o,
        MQ, HID, FFD, FFD, FFD, HID, 0);
    add_ln<<<MQ, 128>>>(h, o, g2, be2, h2);
    tgemm<<<G(MQ, FFD), 256, GEMM_SMEM>>>(h2, m1T, bm1, ff,
        MQ, FFD, HID, HID, HID, FFD, 1);
    tgemm<<<G(MQ, OUTD), 256, GEMM_SMEM>>>(ff, m2T, bm2, out,
        MQ, OUTD, FFD, FFD, FFD, OUTD, 0);
}